// round 1
// baseline (speedup 1.0000x reference)
#include <cuda_runtime.h>

#define BB 8
#define CC 64
#define CQv 8
#define WD 256
#define HD 256
#define NT 1024   // patch tokens
#define MT 512    // Cq*P*P

// Scratch (device globals; no allocation allowed)
__device__ float g_q[BB * MT * NT];     // [b][m][n]
__device__ float g_k[BB * MT * NT];     // [b][m][n]
__device__ float g_v[BB * MT * NT];     // [b][m][n]
__device__ float g_attn[(size_t)BB * NT * NT]; // [b][i][j] energy -> attn
__device__ float g_ot[BB * NT * MT];    // [b][n][m]  (gemm2 output, transposed)

// ---------------------------------------------------------------------------
// Kernel 1: QKV 1x1 conv + patchify into token layout [b][m][n]
// ---------------------------------------------------------------------------
__global__ __launch_bounds__(256) void qkv_kernel(
    const float* __restrict__ x,
    const float* __restrict__ Wq, const float* __restrict__ bq,
    const float* __restrict__ Wk, const float* __restrict__ bk,
    const float* __restrict__ Wv, const float* __restrict__ bv)
{
    __shared__ float sWq[CQv * CC], sWk[CQv * CC], sWv[CQv * CC];
    __shared__ float sbq[CQv], sbk[CQv], sbv[CQv];
    int tid = threadIdx.x;
    for (int i = tid; i < CQv * CC; i += 256) {
        sWq[i] = Wq[i]; sWk[i] = Wk[i]; sWv[i] = Wv[i];
    }
    if (tid < CQv) { sbq[tid] = bq[tid]; sbk[tid] = bk[tid]; sbv[tid] = bv[tid]; }
    __syncthreads();

    int gid = blockIdx.x * 256 + tid;     // pixel id over B*W*H
    int b = gid >> 16;
    int pix = gid & 65535;
    int w = pix >> 8, h = pix & 255;

    const float* xp = x + ((size_t)b * CC) * 65536 + pix;

    float aq[CQv], ak[CQv], av[CQv];
#pragma unroll
    for (int q = 0; q < CQv; q++) { aq[q] = 0.f; ak[q] = 0.f; av[q] = 0.f; }

#pragma unroll 8
    for (int c = 0; c < CC; c++) {
        float xv = xp[(size_t)c * 65536];
#pragma unroll
        for (int q = 0; q < CQv; q++) {
            aq[q] += sWq[q * CC + c] * xv;
            ak[q] += sWk[q * CC + c] * xv;
            av[q] += sWv[q * CC + c] * xv;
        }
    }

    int wp = w >> 3, pa = w & 7, hp = h >> 3, pb = h & 7;
    int fbase = wp * 2048 + hp * 64 + pa * 8 + pb;
#pragma unroll
    for (int q = 0; q < CQv; q++) {
        int f = q * 65536 + fbase;
        int m = f >> 10;
        int n = f & 1023;
        size_t addr = ((size_t)b * MT + m) * NT + n;
        g_q[addr] = aq[q] + sbq[q];
        g_k[addr] = ak[q] + sbk[q];
        g_v[addr] = av[q] + sbv[q];
    }
}

// ---------------------------------------------------------------------------
// Kernel 2: energy[b][i][j] = (1/32) * sum_m q[b][m][i] * k[b][m][j]
// 64x64 tile, BK=16, 256 threads, 4x4 microtile
// ---------------------------------------------------------------------------
__global__ __launch_bounds__(256) void gemm1_kernel()
{
    __shared__ float As[16][68];
    __shared__ float Bs[16][68];
    int b = blockIdx.z;
    int ib = blockIdx.y * 64;   // i (attn row)
    int jb = blockIdx.x * 64;   // j (attn col)
    int tid = threadIdx.x;
    int ry = tid >> 4;          // 0..15 -> i frag group
    int cx = tid & 15;          // 0..15 -> j frag group
    int lr = tid >> 4;          // load row 0..15 (k index)
    int lc = (tid & 15) * 4;    // load col

    const float* qb = g_q + (size_t)b * MT * NT;
    const float* kb = g_k + (size_t)b * MT * NT;

    float acc[4][4];
#pragma unroll
    for (int u = 0; u < 4; u++)
#pragma unroll
        for (int v = 0; v < 4; v++) acc[u][v] = 0.f;

    for (int m0 = 0; m0 < MT; m0 += 16) {
        float4 a4 = *(const float4*)(qb + (size_t)(m0 + lr) * NT + ib + lc);
        float4 b4 = *(const float4*)(kb + (size_t)(m0 + lr) * NT + jb + lc);
        *(float4*)&As[lr][lc] = a4;
        *(float4*)&Bs[lr][lc] = b4;
        __syncthreads();
#pragma unroll
        for (int kk = 0; kk < 16; kk++) {
            float4 af = *(float4*)&As[kk][ry * 4];
            float4 bf = *(float4*)&Bs[kk][cx * 4];
            float ar[4] = {af.x, af.y, af.z, af.w};
            float br[4] = {bf.x, bf.y, bf.z, bf.w};
#pragma unroll
            for (int u = 0; u < 4; u++)
#pragma unroll
                for (int v = 0; v < 4; v++) acc[u][v] += ar[u] * br[v];
        }
        __syncthreads();
    }

    float* cp = g_attn + (size_t)b * NT * NT;
#pragma unroll
    for (int u = 0; u < 4; u++) {
        float4 o;
        o.x = acc[u][0] * 0.03125f;
        o.y = acc[u][1] * 0.03125f;
        o.z = acc[u][2] * 0.03125f;
        o.w = acc[u][3] * 0.03125f;
        *(float4*)(cp + (size_t)(ib + ry * 4 + u) * NT + jb + cx * 4) = o;
    }
}

// ---------------------------------------------------------------------------
// Kernel 3: row softmax over g_attn rows (8192 rows of 1024)
// ---------------------------------------------------------------------------
__global__ __launch_bounds__(256) void softmax_kernel()
{
    __shared__ float redm[8];
    __shared__ float reds[8];
    size_t row = blockIdx.x;
    float4* p = (float4*)(g_attn + row * NT);
    int tid = threadIdx.x;
    float4 v = p[tid];

    float mx = fmaxf(fmaxf(v.x, v.y), fmaxf(v.z, v.w));
#pragma unroll
    for (int o = 16; o; o >>= 1) mx = fmaxf(mx, __shfl_xor_sync(0xffffffffu, mx, o));
    if ((tid & 31) == 0) redm[tid >> 5] = mx;
    __syncthreads();
    mx = redm[0];
#pragma unroll
    for (int i = 1; i < 8; i++) mx = fmaxf(mx, redm[i]);

    v.x = __expf(v.x - mx);
    v.y = __expf(v.y - mx);
    v.z = __expf(v.z - mx);
    v.w = __expf(v.w - mx);
    float s = v.x + v.y + v.z + v.w;
#pragma unroll
    for (int o = 16; o; o >>= 1) s += __shfl_xor_sync(0xffffffffu, s, o);
    if ((tid & 31) == 0) reds[tid >> 5] = s;
    __syncthreads();
    s = reds[0];
#pragma unroll
    for (int i = 1; i < 8; i++) s += reds[i];

    float inv = 1.0f / s;
    v.x *= inv; v.y *= inv; v.z *= inv; v.w *= inv;
    p[tid] = v;
}

// ---------------------------------------------------------------------------
// Kernel 4: o_t[b][j][m] = sum_n v[b][m][n] * attn[b][j][n]
// Both operands k-minor -> transpose-on-load into k-major shared tiles.
// ---------------------------------------------------------------------------
__global__ __launch_bounds__(256) void gemm2_kernel()
{
    __shared__ float As[16][68];   // v tile: As[n][m]
    __shared__ float Bs[16][68];   // attn tile: Bs[n][j]
    int b = blockIdx.z;
    int jb = blockIdx.x * 64;   // attn row block (output token n)
    int mb = blockIdx.y * 64;   // v row block (M)
    int tid = threadIdx.x;
    int ry = tid >> 4;          // j frag group
    int cx = tid & 15;          // m frag group

    int lrow = tid >> 2;        // 0..63
    int cch = (tid & 3) * 4;    // n-chunk within 16

    const float* vb = g_v + (size_t)b * MT * NT;
    const float* ab = g_attn + (size_t)b * NT * NT;

    float acc[4][4];
#pragma unroll
    for (int u = 0; u < 4; u++)
#pragma unroll
        for (int v = 0; v < 4; v++) acc[u][v] = 0.f;

    for (int n0 = 0; n0 < NT; n0 += 16) {
        float4 a4 = *(const float4*)(vb + (size_t)(mb + lrow) * NT + n0 + cch);
        float4 b4 = *(const float4*)(ab + (size_t)(jb + lrow) * NT + n0 + cch);
        As[cch + 0][lrow] = a4.x;
        As[cch + 1][lrow] = a4.y;
        As[cch + 2][lrow] = a4.z;
        As[cch + 3][lrow] = a4.w;
        Bs[cch + 0][lrow] = b4.x;
        Bs[cch + 1][lrow] = b4.y;
        Bs[cch + 2][lrow] = b4.z;
        Bs[cch + 3][lrow] = b4.w;
        __syncthreads();
#pragma unroll
        for (int kk = 0; kk < 16; kk++) {
            float4 af = *(float4*)&As[kk][cx * 4];   // m frag
            float4 bf = *(float4*)&Bs[kk][ry * 4];   // j frag
            float ar[4] = {af.x, af.y, af.z, af.w};
            float br[4] = {bf.x, bf.y, bf.z, bf.w};
#pragma unroll
            for (int u = 0; u < 4; u++)       // j
#pragma unroll
                for (int v = 0; v < 4; v++)   // m
                    acc[u][v] += br[u] * ar[v];
        }
        __syncthreads();
    }

    // store transposed: o_t[b][j][m]
    float* cp = g_ot + (size_t)b * NT * MT;
#pragma unroll
    for (int u = 0; u < 4; u++) {
        float4 o;
        o.x = acc[u][0]; o.y = acc[u][1]; o.z = acc[u][2]; o.w = acc[u][3];
        *(float4*)(cp + (size_t)(jb + ry * 4 + u) * MT + mb + cx * 4) = o;
    }
}

// ---------------------------------------------------------------------------
// Kernel 5: output 1x1 conv + gamma residual
// ---------------------------------------------------------------------------
__global__ __launch_bounds__(256) void out_kernel(
    const float* __restrict__ x,
    const float* __restrict__ Wo, const float* __restrict__ bo,
    const float* __restrict__ gamma, float* __restrict__ out)
{
    __shared__ float sWo[CC * CQv];
    __shared__ float sbo[CC];
    int tid = threadIdx.x;
    for (int i = tid; i < CC * CQv; i += 256) sWo[i] = Wo[i];
    if (tid < CC) sbo[tid] = bo[tid];
    __syncthreads();

    int gid = blockIdx.x * 256 + tid;
    int b = gid >> 16;
    int pix = gid & 65535;

    float s[CQv];
#pragma unroll
    for (int q = 0; q < CQv; q++) {
        int g = q * 65536 + pix;
        int n = g >> 9;
        int m = g & 511;
        s[q] = g_ot[((size_t)b * NT + n) * MT + m];
    }
    float gm = __ldg(gamma);

#pragma unroll
    for (int co = 0; co < CC; co++) {
        float acc = sbo[co];
#pragma unroll
        for (int q = 0; q < CQv; q++) acc += sWo[co * CQv + q] * s[q];
        size_t a = ((size_t)b * CC + co) * 65536 + pix;
        out[a] = gm * acc + x[a];
    }
}

// ---------------------------------------------------------------------------
extern "C" void kernel_launch(void* const* d_in, const int* in_sizes, int n_in,
                              void* d_out, int out_size)
{
    const float* x  = (const float*)d_in[0];
    const float* Wq = (const float*)d_in[1];
    const float* bq = (const float*)d_in[2];
    const float* Wk = (const float*)d_in[3];
    const float* bk = (const float*)d_in[4];
    const float* Wv = (const float*)d_in[5];
    const float* bv = (const float*)d_in[6];
    const float* Wo = (const float*)d_in[7];
    const float* bo = (const float*)d_in[8];
    const float* gm = (const float*)d_in[9];
    float* out = (float*)d_out;

    qkv_kernel<<<2048, 256>>>(x, Wq, bq, Wk, bk, Wv, bv);
    gemm1_kernel<<<dim3(16, 16, 8), 256>>>();
    softmax_kernel<<<8192, 256>>>();
    gemm2_kernel<<<dim3(16, 8, 8), 256>>>();
    out_kernel<<<2048, 256>>>(x, Wo, bo, gm, out);
}

// round 2
// speedup vs baseline: 1.1883x; 1.1883x over previous
#include <cuda_runtime.h>

#define BB 8
#define CC 64
#define CQv 8
#define NT 1024   // patch tokens
#define MT 512    // Cq*P*P

// Scratch (device globals; no allocation allowed)
__device__ float g_q[BB * MT * NT];              // [b][m][i]   (i = query token)
__device__ float g_k[BB * MT * NT];              // [b][m][n]   (n = key token)
__device__ float g_vt[BB * NT * MT];             // [b][n][m]   (v transposed)
__device__ float g_attn[(size_t)BB * NT * NT];   // [b][n][i]   e_t -> exp(e_t - max)
__device__ float g_sums[BB * NT];                // per-(b,i) softmax denominators
__device__ float g_ot[BB * NT * MT];             // [b][i][m]

// ---------------------------------------------------------------------------
// Kernel 1: QKV 1x1 conv + patchify. q,k in [m][token]; v in [n][m].
// ---------------------------------------------------------------------------
__global__ __launch_bounds__(256) void qkv_kernel(
    const float* __restrict__ x,
    const float* __restrict__ Wq, const float* __restrict__ bq,
    const float* __restrict__ Wk, const float* __restrict__ bk,
    const float* __restrict__ Wv, const float* __restrict__ bv)
{
    __shared__ float sWq[CQv * CC], sWk[CQv * CC], sWv[CQv * CC];
    __shared__ float sbq[CQv], sbk[CQv], sbv[CQv];
    int tid = threadIdx.x;
    for (int i = tid; i < CQv * CC; i += 256) {
        sWq[i] = Wq[i]; sWk[i] = Wk[i]; sWv[i] = Wv[i];
    }
    if (tid < CQv) { sbq[tid] = bq[tid]; sbk[tid] = bk[tid]; sbv[tid] = bv[tid]; }
    __syncthreads();

    int gid = blockIdx.x * 256 + tid;     // pixel id over B*W*H
    int b = gid >> 16;
    int pix = gid & 65535;
    int w = pix >> 8, h = pix & 255;

    const float* xp = x + ((size_t)b * CC) * 65536 + pix;

    float aq[CQv], ak[CQv], av[CQv];
#pragma unroll
    for (int q = 0; q < CQv; q++) { aq[q] = 0.f; ak[q] = 0.f; av[q] = 0.f; }

#pragma unroll 8
    for (int c = 0; c < CC; c++) {
        float xv = xp[(size_t)c * 65536];
#pragma unroll
        for (int q = 0; q < CQv; q++) {
            aq[q] += sWq[q * CC + c] * xv;
            ak[q] += sWk[q * CC + c] * xv;
            av[q] += sWv[q * CC + c] * xv;
        }
    }

    int wp = w >> 3, pa = w & 7, hp = h >> 3, pb = h & 7;
    int fbase = wp * 2048 + hp * 64 + pa * 8 + pb;
#pragma unroll
    for (int q = 0; q < CQv; q++) {
        int f = q * 65536 + fbase;
        int m = f >> 10;
        int n = f & 1023;
        size_t addr = ((size_t)b * MT + m) * NT + n;
        g_q[addr] = aq[q] + sbq[q];
        g_k[addr] = ak[q] + sbk[q];
        g_vt[((size_t)b * NT + n) * MT + m] = av[q] + sbv[q];
    }
}

// ---------------------------------------------------------------------------
// Kernel 2: e_t[b][n][i] = (1/32) * sum_m k[b][m][n] * q[b][m][i]
// 128x128 tile, BK=8, 256 threads, 8x8 microtile, double-buffered smem.
// ---------------------------------------------------------------------------
__global__ __launch_bounds__(256) void gemm1_kernel()
{
    __shared__ float As[2][8][128];   // k tile (rows of C = n)
    __shared__ float Bs[2][8][128];   // q tile (cols of C = i)
    int b  = blockIdx.z;
    int nb = blockIdx.y * 128;
    int ib = blockIdx.x * 128;
    int tid = threadIdx.x;
    int lr = tid >> 5;              // 0..7 (k-row)
    int lc = (tid & 31) * 4;        // 0..124
    int tx = tid & 15;              // col frag
    int ty = tid >> 4;              // row frag

    const float* Ap = g_k + (size_t)b * MT * NT;
    const float* Bp = g_q + (size_t)b * MT * NT;

    float acc[8][8];
#pragma unroll
    for (int u = 0; u < 8; u++)
#pragma unroll
        for (int v = 0; v < 8; v++) acc[u][v] = 0.f;

    // prologue
    {
        float4 a4 = *(const float4*)(Ap + (size_t)lr * NT + nb + lc);
        float4 b4 = *(const float4*)(Bp + (size_t)lr * NT + ib + lc);
        *(float4*)&As[0][lr][lc] = a4;
        *(float4*)&Bs[0][lr][lc] = b4;
    }
    __syncthreads();

    int s = 0;
    const int T = MT / 8;
    for (int t = 1; t <= T; t++) {
        float4 a4, b4;
        bool more = (t < T);
        if (more) {
            int k0 = t * 8;
            a4 = *(const float4*)(Ap + (size_t)(k0 + lr) * NT + nb + lc);
            b4 = *(const float4*)(Bp + (size_t)(k0 + lr) * NT + ib + lc);
        }
#pragma unroll
        for (int kk = 0; kk < 8; kk++) {
            float ar[8], br[8];
            *(float4*)(ar)     = *(float4*)&As[s][kk][ty * 4];
            *(float4*)(ar + 4) = *(float4*)&As[s][kk][64 + ty * 4];
            *(float4*)(br)     = *(float4*)&Bs[s][kk][tx * 4];
            *(float4*)(br + 4) = *(float4*)&Bs[s][kk][64 + tx * 4];
#pragma unroll
            for (int u = 0; u < 8; u++)
#pragma unroll
                for (int v = 0; v < 8; v++) acc[u][v] += ar[u] * br[v];
        }
        if (more) {
            s ^= 1;
            *(float4*)&As[s][lr][lc] = a4;
            *(float4*)&Bs[s][lr][lc] = b4;
            __syncthreads();
        }
    }

    const float S = 0.03125f;
    float* cp = g_attn + (size_t)b * NT * NT;
#pragma unroll
    for (int u = 0; u < 8; u++) {
        int r = (u < 4) ? (ty * 4 + u) : (64 + ty * 4 + u - 4);
        float4 o0, o1;
        o0.x = acc[u][0] * S; o0.y = acc[u][1] * S; o0.z = acc[u][2] * S; o0.w = acc[u][3] * S;
        o1.x = acc[u][4] * S; o1.y = acc[u][5] * S; o1.z = acc[u][6] * S; o1.w = acc[u][7] * S;
        *(float4*)(cp + (size_t)(nb + r) * NT + ib + tx * 4)      = o0;
        *(float4*)(cp + (size_t)(nb + r) * NT + ib + 64 + tx * 4) = o1;
    }
}

// ---------------------------------------------------------------------------
// Kernel 3: column softmax over e_t: for each (b,i), over n (rows).
// Writes exp(e - max) in place; stores the sum to g_sums (normalized later
// in gemm2 epilogue). Block: 32 i-columns x 8 n-groups.
// ---------------------------------------------------------------------------
__global__ __launch_bounds__(256) void softmax_kernel()
{
    __shared__ float red[8][33];
    int b  = blockIdx.y;
    int tid = threadIdx.x;
    int il = tid & 31;
    int ng = tid >> 5;
    int i = blockIdx.x * 32 + il;

    float* base = g_attn + (size_t)b * NT * NT + i;
    int n0 = ng * 128;

    float mx = -1e30f;
#pragma unroll 8
    for (int n = 0; n < 128; n++)
        mx = fmaxf(mx, base[(size_t)(n0 + n) * NT]);
    red[ng][il] = mx;
    __syncthreads();
    mx = red[0][il];
#pragma unroll
    for (int g = 1; g < 8; g++) mx = fmaxf(mx, red[g][il]);
    __syncthreads();

    float sum = 0.f;
#pragma unroll 8
    for (int n = 0; n < 128; n++) {
        size_t a = (size_t)(n0 + n) * NT;
        float e = __expf(base[a] - mx);
        base[a] = e;
        sum += e;
    }
    red[ng][il] = sum;
    __syncthreads();
    if (ng == 0) {
        float s = red[0][il];
#pragma unroll
        for (int g = 1; g < 8; g++) s += red[g][il];
        g_sums[b * NT + i] = s;
    }
}

// ---------------------------------------------------------------------------
// Kernel 4: o[b][i][m] = (1/sum_i) * sum_n attn[b][n][i] * vt[b][n][m]
// Same template as gemm1; K=1024. Rows of C = i (from attn), cols = m (vt).
// ---------------------------------------------------------------------------
__global__ __launch_bounds__(256) void gemm2_kernel()
{
    __shared__ float As[2][8][128];   // attn tile (rows of C = i)
    __shared__ float Bs[2][8][128];   // vt tile   (cols of C = m)
    int b  = blockIdx.z;
    int ib = blockIdx.x * 128;
    int mb = blockIdx.y * 128;
    int tid = threadIdx.x;
    int lr = tid >> 5;
    int lc = (tid & 31) * 4;
    int tx = tid & 15;
    int ty = tid >> 4;

    const float* Ap = g_attn + (size_t)b * NT * NT;
    const float* Bp = g_vt + (size_t)b * NT * MT;

    float acc[8][8];
#pragma unroll
    for (int u = 0; u < 8; u++)
#pragma unroll
        for (int v = 0; v < 8; v++) acc[u][v] = 0.f;

    {
        float4 a4 = *(const float4*)(Ap + (size_t)lr * NT + ib + lc);
        float4 b4 = *(const float4*)(Bp + (size_t)lr * MT + mb + lc);
        *(float4*)&As[0][lr][lc] = a4;
        *(float4*)&Bs[0][lr][lc] = b4;
    }
    __syncthreads();

    int s = 0;
    const int T = NT / 8;
    for (int t = 1; t <= T; t++) {
        float4 a4, b4;
        bool more = (t < T);
        if (more) {
            int k0 = t * 8;
            a4 = *(const float4*)(Ap + (size_t)(k0 + lr) * NT + ib + lc);
            b4 = *(const float4*)(Bp + (size_t)(k0 + lr) * MT + mb + lc);
        }
#pragma unroll
        for (int kk = 0; kk < 8; kk++) {
            float ar[8], br[8];
            *(float4*)(ar)     = *(float4*)&As[s][kk][ty * 4];
            *(float4*)(ar + 4) = *(float4*)&As[s][kk][64 + ty * 4];
            *(float4*)(br)     = *(float4*)&Bs[s][kk][tx * 4];
            *(float4*)(br + 4) = *(float4*)&Bs[s][kk][64 + tx * 4];
#pragma unroll
            for (int u = 0; u < 8; u++)
#pragma unroll
                for (int v = 0; v < 8; v++) acc[u][v] += ar[u] * br[v];
        }
        if (more) {
            s ^= 1;
            *(float4*)&As[s][lr][lc] = a4;
            *(float4*)&Bs[s][lr][lc] = b4;
            __syncthreads();
        }
    }

    const float* sums = g_sums + b * NT;
    float* cp = g_ot + (size_t)b * NT * MT;
#pragma unroll
    for (int u = 0; u < 8; u++) {
        int r = (u < 4) ? (ty * 4 + u) : (64 + ty * 4 + u - 4);
        float inv = 1.0f / sums[ib + r];
        float4 o0, o1;
        o0.x = acc[u][0] * inv; o0.y = acc[u][1] * inv; o0.z = acc[u][2] * inv; o0.w = acc[u][3] * inv;
        o1.x = acc[u][4] * inv; o1.y = acc[u][5] * inv; o1.z = acc[u][6] * inv; o1.w = acc[u][7] * inv;
        *(float4*)(cp + (size_t)(ib + r) * MT + mb + tx * 4)      = o0;
        *(float4*)(cp + (size_t)(ib + r) * MT + mb + 64 + tx * 4) = o1;
    }
}

// ---------------------------------------------------------------------------
// Kernel 5: output 1x1 conv + gamma residual
// ---------------------------------------------------------------------------
__global__ __launch_bounds__(256) void out_kernel(
    const float* __restrict__ x,
    const float* __restrict__ Wo, const float* __restrict__ bo,
    const float* __restrict__ gamma, float* __restrict__ out)
{
    __shared__ float sWo[CC * CQv];
    __shared__ float sbo[CC];
    int tid = threadIdx.x;
    for (int i = tid; i < CC * CQv; i += 256) sWo[i] = Wo[i];
    if (tid < CC) sbo[tid] = bo[tid];
    __syncthreads();

    int gid = blockIdx.x * 256 + tid;
    int b = gid >> 16;
    int pix = gid & 65535;

    float s[CQv];
#pragma unroll
    for (int q = 0; q < CQv; q++) {
        int g = q * 65536 + pix;
        int n = g >> 9;
        int m = g & 511;
        s[q] = g_ot[((size_t)b * NT + n) * MT + m];
    }
    float gm = __ldg(gamma);

#pragma unroll
    for (int co = 0; co < CC; co++) {
        float acc = sbo[co];
#pragma unroll
        for (int q = 0; q < CQv; q++) acc += sWo[co * CQv + q] * s[q];
        size_t a = ((size_t)b * CC + co) * 65536 + pix;
        out[a] = gm * acc + x[a];
    }
}

// ---------------------------------------------------------------------------
extern "C" void kernel_launch(void* const* d_in, const int* in_sizes, int n_in,
                              void* d_out, int out_size)
{
    const float* x  = (const float*)d_in[0];
    const float* Wq = (const float*)d_in[1];
    const float* bq = (const float*)d_in[2];
    const float* Wk = (const float*)d_in[3];
    const float* bk = (const float*)d_in[4];
    const float* Wv = (const float*)d_in[5];
    const float* bv = (const float*)d_in[6];
    const float* Wo = (const float*)d_in[7];
    const float* bo = (const float*)d_in[8];
    const float* gm = (const float*)d_in[9];
    float* out = (float*)d_out;

    qkv_kernel<<<2048, 256>>>(x, Wq, bq, Wk, bk, Wv, bv);
    gemm1_kernel<<<dim3(8, 8, 8), 256>>>();
    softmax_kernel<<<dim3(32, 8), 256>>>();
    gemm2_kernel<<<dim3(8, 4, 8), 256>>>();
    out_kernel<<<2048, 256>>>(x, Wo, bo, gm, out);
}